// round 4
// baseline (speedup 1.0000x reference)
#include <cuda_runtime.h>
#include <math.h>

#define HWSZ 12544      // 112*112
#define IMGW 112
#define NB   16
#define EPSV 1e-5f

typedef unsigned long long u64;

#define FMA_F32X2(d, a, b, c) \
    asm("fma.rn.f32x2 %0, %1, %2, %3;" : "=l"(d) : "l"(a), "l"(b), "l"(c))
#define UNPK_F32X2(lo, hi, v) \
    asm("mov.b64 {%0, %1}, %2;" : "=f"(lo), "=f"(hi) : "l"(v))

// ---- scratch (tiny) ----
__device__ float g_pooled[NB * 64];
__device__ float g_sum1[NB * 64];      // post-act x1 channel sums
__device__ float g_sum2[NB * 64];      // post-act x2 channel sums
__device__ float g_gates[NB * 128];

__device__ __forceinline__ float sigmoidf_(float x) { return 1.f / (1.f + expf(-x)); }

// ---- mean over HW per (b,c) + zero sums: grid 1024 x 256 ----
__global__ __launch_bounds__(256) void pool1_kernel(const float* __restrict__ x) {
    int bc = blockIdx.x;
    if (threadIdx.x == 0) { g_sum1[bc] = 0.f; g_sum2[bc] = 0.f; }
    const float4* p = (const float4*)(x + (size_t)bc * HWSZ);
    float s = 0.f;
    for (int i = threadIdx.x; i < HWSZ / 4; i += 256) {
        float4 v = p[i];
        s += v.x + v.y + v.z + v.w;
    }
    for (int o = 16; o; o >>= 1) s += __shfl_xor_sync(0xffffffffu, s, o);
    __shared__ float red[8];
    if ((threadIdx.x & 31) == 0) red[threadIdx.x >> 5] = s;
    __syncthreads();
    if (threadIdx.x < 8) {
        s = red[threadIdx.x];
        for (int o = 4; o; o >>= 1) s += __shfl_xor_sync(0xffu, s, o);
        if (threadIdx.x == 0) g_pooled[bc] = s * (1.f / (float)HWSZ);
    }
}

// ---- dynamic 1x1 conv via packed f32x2 FMA ----
// tile: 64 outputs x 256 pixels; per lane 8 out x 8 px (4 pixel-pairs)
// smem: ks2 [64i][128] (k duplicated {k,k}) + xs [64i][256px]
extern __shared__ float conv1_smem[];
__global__ __launch_bounds__(256, 2) void conv1_kernel(
    const float* __restrict__ x,
    const float* __restrict__ rw1, const float* __restrict__ rb1,
    const float* __restrict__ w1,
    const float* __restrict__ g1, const float* __restrict__ b1,
    const float* __restrict__ m1, const float* __restrict__ v1,
    float* __restrict__ out) {
    float* ks2 = conv1_smem;          // 8192 floats (dup k)
    float* xs  = conv1_smem + 8192;   // 16384 floats
    __shared__ float r1s[4];
    int b = blockIdx.y;
    int p0 = blockIdx.x * 256;
    int tid = threadIdx.x;

    {
        float4* xdst = (float4*)xs;
#pragma unroll
        for (int i = 0; i < 16; i++) {
            int idx = tid + 256 * i;           // f4 index in [0,4096)
            int row = idx >> 6, col = (idx & 63) << 2;
            xdst[idx] = *(const float4*)&x[((size_t)(b * 64 + row)) * HWSZ + p0 + col];
        }
    }
    if (tid < 4) {
        float a = rb1[tid];
        for (int i = 0; i < 64; i++) a += g_pooled[b * 64 + i] * rw1[tid * 64 + i];
        r1s[tid] = sigmoidf_(a);
    }
    __syncthreads();
    // build mixed 1x1 kernel in smem, duplicated: ks2[i*128 + 2o] = ks2[..+1] = k
#pragma unroll
    for (int k = 0; k < 16; k++) {
        int idx = tid + 256 * k;
        int i = idx >> 6, o = idx & 63;
        float a = 0.f;
#pragma unroll
        for (int e = 0; e < 4; e++) a += r1s[e] * __ldg(&w1[e * 4096 + o * 64 + i]);
        float v = a * (g1[o] * rsqrtf(v1[o] + EPSV));
        ks2[i * 128 + 2 * o]     = v;
        ks2[i * 128 + 2 * o + 1] = v;
    }
    __syncthreads();

    int og = (tid >> 5) << 3;    // warp -> 8 outputs
    int q0 = (tid & 31) << 2;    // lane -> px [q0..q0+3] and [q0+128..q0+131]
    u64 acc[8][4];
#pragma unroll
    for (int a = 0; a < 8; a++)
#pragma unroll
        for (int p = 0; p < 4; p++) acc[a][p] = 0ull;

#pragma unroll 4
    for (int i = 0; i < 64; i++) {
        longlong2 xa = *(const longlong2*)&xs[(i << 8) + q0];
        longlong2 xb = *(const longlong2*)&xs[(i << 8) + 128 + q0];
        const float* kr = &ks2[i * 128 + og * 2];
        longlong2 k01 = *(const longlong2*)&kr[0];
        longlong2 k23 = *(const longlong2*)&kr[4];
        longlong2 k45 = *(const longlong2*)&kr[8];
        longlong2 k67 = *(const longlong2*)&kr[12];
        u64 kk[8] = {(u64)k01.x, (u64)k01.y, (u64)k23.x, (u64)k23.y,
                     (u64)k45.x, (u64)k45.y, (u64)k67.x, (u64)k67.y};
        u64 xx[4] = {(u64)xa.x, (u64)xa.y, (u64)xb.x, (u64)xb.y};
#pragma unroll
        for (int a = 0; a < 8; a++)
#pragma unroll
            for (int p = 0; p < 4; p++)
                FMA_F32X2(acc[a][p], kk[a], xx[p], acc[a][p]);
    }

#pragma unroll
    for (int a = 0; a < 8; a++) {
        int o = og + a;
        float sc = g1[o] * rsqrtf(v1[o] + EPSV);
        float sh = b1[o] - m1[o] * sc;
        float p0f, p1f, p2f, p3f, p4f, p5f, p6f, p7f;
        UNPK_F32X2(p0f, p1f, acc[a][0]);
        UNPK_F32X2(p2f, p3f, acc[a][1]);
        UNPK_F32X2(p4f, p5f, acc[a][2]);
        UNPK_F32X2(p6f, p7f, acc[a][3]);
        float4 r0, r1q;
        r0.x = fmaxf(p0f + sh, 0.f); r0.y = fmaxf(p1f + sh, 0.f);
        r0.z = fmaxf(p2f + sh, 0.f); r0.w = fmaxf(p3f + sh, 0.f);
        r1q.x = fmaxf(p4f + sh, 0.f); r1q.y = fmaxf(p5f + sh, 0.f);
        r1q.z = fmaxf(p6f + sh, 0.f); r1q.w = fmaxf(p7f + sh, 0.f);
        float* op = out + ((size_t)(b * 128 + o)) * HWSZ + p0;
        *(float4*)&op[q0] = r0;
        *(float4*)&op[128 + q0] = r1q;
        float s = r0.x + r0.y + r0.z + r0.w + r1q.x + r1q.y + r1q.z + r1q.w;
        for (int o2 = 16; o2; o2 >>= 1) s += __shfl_xor_sync(0xffffffffu, s, o2);
        if ((tid & 31) == 0) atomicAdd(&g_sum1[b * 64 + o], s);
    }
}

// ---- dynamic 3x3 depthwise (k2 mix fused) + BN + ReLU + channel-sum ----
// grid (7 strips, NB*64), block 224; strip = 16 rows x 112 cols
#define DWST 120
__global__ __launch_bounds__(224) void dw_kernel(
    const float* __restrict__ rw2, const float* __restrict__ rb2,
    const float* __restrict__ w2,
    const float* __restrict__ g2, const float* __restrict__ b2,
    const float* __restrict__ m2, const float* __restrict__ v2,
    float* __restrict__ out) {
    __shared__ float sm[18 * DWST];
    __shared__ float r2s[4];
    __shared__ float kk[9];
    __shared__ float sh_bias;
    __shared__ float red[7];

    int bc = blockIdx.y;
    int b = bc >> 6, c = bc & 63;
    const float* in = out + ((size_t)(b * 128 + c)) * HWSZ;       // x1 channel
    float* op = out + ((size_t)(b * 128 + 64 + c)) * HWSZ;        // x2 channel
    int tid = threadIdx.x;
    int y0 = blockIdx.x * 16;

    if (tid < 4) {
        float a = rb2[tid];
        for (int cc = 0; cc < 64; cc++)
            a += g_sum1[b * 64 + cc] * (1.f / (float)HWSZ) * rw2[tid * 64 + cc];
        r2s[tid] = sigmoidf_(a);
    }
    // load 18 rows x 28 quads = 504 f4 with 224 threads
    for (int i = tid; i < 504; i += 224) {
        int r = i / 28, q = i % 28;
        int gy = y0 - 1 + r;
        float4 v;
        if (gy >= 0 && gy < IMGW) v = *(const float4*)&in[gy * IMGW + q * 4];
        else v = make_float4(0.f, 0.f, 0.f, 0.f);
        *(float4*)&sm[r * DWST + 4 + q * 4] = v;
    }
    for (int r = tid; r < 18; r += 224) { sm[r * DWST + 3] = 0.f; sm[r * DWST + 116] = 0.f; }
    __syncthreads();
    if (tid < 9) {
        float a = 0.f;
#pragma unroll
        for (int e = 0; e < 4; e++) a += r2s[e] * w2[e * 576 + c * 9 + tid];
        kk[tid] = a * (g2[c] * rsqrtf(v2[c] + EPSV));
    }
    if (tid == 9) {
        float sc = g2[c] * rsqrtf(v2[c] + EPSV);
        sh_bias = b2[c] - m2[c] * sc;
    }
    __syncthreads();

    int q = tid % 28;            // quad col
    int rr = tid / 28;           // 0..7
    int xb = 4 + q * 4;
    float tsum = 0.f;

#pragma unroll
    for (int half = 0; half < 2; half++) {
        int orow = rr + half * 8;               // output row in strip (0..15)
        float acc0 = sh_bias, acc1 = sh_bias, acc2 = sh_bias, acc3 = sh_bias;
#pragma unroll
        for (int dr = 0; dr < 3; dr++) {
            const float* row = &sm[(orow + dr) * DWST];
            float l = row[xb - 1];
            float4 m = *(const float4*)&row[xb];
            float rgt = row[xb + 4];
            float k0 = kk[dr * 3 + 0], k1 = kk[dr * 3 + 1], k2 = kk[dr * 3 + 2];
            acc0 = fmaf(k0, l,   fmaf(k1, m.x, fmaf(k2, m.y, acc0)));
            acc1 = fmaf(k0, m.x, fmaf(k1, m.y, fmaf(k2, m.z, acc1)));
            acc2 = fmaf(k0, m.y, fmaf(k1, m.z, fmaf(k2, m.w, acc2)));
            acc3 = fmaf(k0, m.z, fmaf(k1, m.w, fmaf(k2, rgt, acc3)));
        }
        float4 r;
        r.x = fmaxf(acc0, 0.f); r.y = fmaxf(acc1, 0.f);
        r.z = fmaxf(acc2, 0.f); r.w = fmaxf(acc3, 0.f);
        *(float4*)&op[(y0 + orow) * IMGW + q * 4] = r;
        tsum += r.x + r.y + r.z + r.w;
    }

    for (int o = 16; o; o >>= 1) tsum += __shfl_xor_sync(0xffffffffu, tsum, o);
    if ((tid & 31) == 0) red[tid >> 5] = tsum;
    __syncthreads();
    if (tid < 7) {
        float s = red[tid];
        for (int o = 4; o; o >>= 1) s += __shfl_xor_sync(0x7fu, s, o);
        if (tid == 0) atomicAdd(&g_sum2[bc], s);
    }
}

// ---- SE MLP -> gates: grid NB x 128, weights staged in smem ----
__global__ __launch_bounds__(128) void se_kernel(
    const float* __restrict__ sw1, const float* __restrict__ sb1,
    const float* __restrict__ sw2, const float* __restrict__ sb2) {
    int b = blockIdx.x;
    int tid = threadIdx.x;
    __shared__ float w1s[32 * 128];
    __shared__ float w2s[128 * 32];
    __shared__ float sm[128];
    __shared__ float h[32];
#pragma unroll
    for (int k = 0; k < 8; k++) {
        ((float4*)w1s)[tid + 128 * k] = ((const float4*)sw1)[tid + 128 * k];
        ((float4*)w2s)[tid + 128 * k] = ((const float4*)sw2)[tid + 128 * k];
    }
    sm[tid] = (tid < 64 ? g_sum1[b * 64 + tid] : g_sum2[b * 64 + tid - 64]) * (1.f / (float)HWSZ);
    __syncthreads();
    {
        int j = tid >> 2, l4 = tid & 3;
        float a = 0.f;
#pragma unroll
        for (int c = 0; c < 32; c++) a += w1s[j * 128 + l4 * 32 + c] * sm[l4 * 32 + c];
        a += __shfl_xor_sync(0xffffffffu, a, 1);
        a += __shfl_xor_sync(0xffffffffu, a, 2);
        if (l4 == 0) h[j] = fmaxf(a + sb1[j], 0.f);
    }
    __syncthreads();
    float a = sb2[tid];
#pragma unroll
    for (int j = 0; j < 32; j++) a += w2s[tid * 32 + j] * h[j];
    g_gates[b * 128 + tid] = sigmoidf_(a);
}

// ---- in-place gate scaling: grid (14, 2048) x 224, one f4/thread ----
__global__ __launch_bounds__(224) void scale_kernel(float* __restrict__ out) {
    int bc = blockIdx.y;
    int fq = blockIdx.x * 224 + threadIdx.x;     // 0..3135
    float g = __ldg(&g_gates[bc]);
    float4* p = ((float4*)out) + (size_t)bc * (HWSZ / 4) + fq;
    float4 v = *p;
    v.x *= g; v.y *= g; v.z *= g; v.w *= g;
    *p = v;
}

// ---------------------------------------------------------------
extern "C" void kernel_launch(void* const* d_in, const int* in_sizes, int n_in,
                              void* d_out, int out_size) {
    const float* x    = (const float*)d_in[0];
    const float* rw1  = (const float*)d_in[1];
    const float* rb1  = (const float*)d_in[2];
    const float* w1   = (const float*)d_in[3];
    const float* bn1g = (const float*)d_in[4];
    const float* bn1b = (const float*)d_in[5];
    const float* bn1m = (const float*)d_in[6];
    const float* bn1v = (const float*)d_in[7];
    const float* rw2  = (const float*)d_in[8];
    const float* rb2  = (const float*)d_in[9];
    const float* w2   = (const float*)d_in[10];
    const float* bn2g = (const float*)d_in[11];
    const float* bn2b = (const float*)d_in[12];
    const float* bn2m = (const float*)d_in[13];
    const float* bn2v = (const float*)d_in[14];
    const float* sw1  = (const float*)d_in[15];
    const float* sb1  = (const float*)d_in[16];
    const float* sw2  = (const float*)d_in[17];
    const float* sb2  = (const float*)d_in[18];
    float* out = (float*)d_out;

    const int conv1_smem_bytes = (8192 + 16384) * sizeof(float);
    cudaFuncSetAttribute(conv1_kernel, cudaFuncAttributeMaxDynamicSharedMemorySize,
                         conv1_smem_bytes);

    pool1_kernel<<<NB * 64, 256>>>(x);
    conv1_kernel<<<dim3(HWSZ / 256, NB), 256, conv1_smem_bytes>>>(
        x, rw1, rb1, w1, bn1g, bn1b, bn1m, bn1v, out);
    dw_kernel<<<dim3(7, NB * 64), 224>>>(
        rw2, rb2, w2, bn2g, bn2b, bn2m, bn2v, out);
    se_kernel<<<NB, 128>>>(sw1, sb1, sw2, sb2);
    scale_kernel<<<dim3(14, NB * 128), 224>>>(out);
}

// round 5
// speedup vs baseline: 1.9157x; 1.9157x over previous
#include <cuda_runtime.h>
#include <math.h>

#define HWSZ 12544      // 112*112
#define IMGW 112
#define NB   16
#define EPSV 1e-5f

// ---- scratch (tiny) ----
__device__ float g_pooled[NB * 64];
__device__ float g_k1[NB * 64 * 64];   // [b][i][o], BN1 scale folded
__device__ float g_sum1[NB * 64];      // post-act x1 channel sums
__device__ float g_sum2[NB * 64];      // post-act x2 channel sums
__device__ float g_gates[NB * 128];

__device__ __forceinline__ float sigmoidf_(float x) { return 1.f / (1.f + expf(-x)); }

// ---- mean over HW per (b,c) + zero sums: grid 1024 x 256 ----
__global__ __launch_bounds__(256) void pool1_kernel(const float* __restrict__ x) {
    int bc = blockIdx.x;
    if (threadIdx.x == 0) { g_sum1[bc] = 0.f; g_sum2[bc] = 0.f; }
    const float4* p = (const float4*)(x + (size_t)bc * HWSZ);
    float s = 0.f;
    for (int i = threadIdx.x; i < HWSZ / 4; i += 256) {
        float4 v = p[i];
        s += v.x + v.y + v.z + v.w;
    }
    for (int o = 16; o; o >>= 1) s += __shfl_xor_sync(0xffffffffu, s, o);
    __shared__ float red[8];
    if ((threadIdx.x & 31) == 0) red[threadIdx.x >> 5] = s;
    __syncthreads();
    if (threadIdx.x < 8) {
        s = red[threadIdx.x];
        for (int o = 4; o; o >>= 1) s += __shfl_xor_sync(0xffu, s, o);
        if (threadIdx.x == 0) g_pooled[bc] = s * (1.f / (float)HWSZ);
    }
}

// ---- r1 + mixed 1x1 kernel (BN1 scale folded): grid NB x 256 ----
__global__ __launch_bounds__(256) void build_k1_kernel(
    const float* __restrict__ rw1, const float* __restrict__ rb1,
    const float* __restrict__ w1,
    const float* __restrict__ g1, const float* __restrict__ v1) {
    int b = blockIdx.x;
    __shared__ float r1s[4];
    if (threadIdx.x < 4) {
        int e = threadIdx.x;
        float a = rb1[e];
        for (int i = 0; i < 64; i++) a += g_pooled[b * 64 + i] * rw1[e * 64 + i];
        r1s[e] = sigmoidf_(a);
    }
    __syncthreads();
    for (int idx = threadIdx.x; idx < 4096; idx += 256) {
        int i = idx >> 6, o = idx & 63;
        float a = 0.f;
#pragma unroll
        for (int e = 0; e < 4; e++) a += r1s[e] * w1[e * 4096 + o * 64 + i];
        float sc = g1[o] * rsqrtf(v1[o] + EPSV);
        g_k1[b * 4096 + idx] = a * sc;    // layout [i][o]
    }
}

// ---- dynamic 1x1 conv + BN + ReLU + channel-sum (round-2 proven version) ----
// tile: 64 outputs x 256 pixels; per lane 8 out x 8 px. grid (49, NB) x 256
extern __shared__ float conv1_smem[];
__global__ __launch_bounds__(256, 2) void conv1_kernel(
    const float* __restrict__ x,
    const float* __restrict__ g1, const float* __restrict__ b1,
    const float* __restrict__ m1, const float* __restrict__ v1,
    float* __restrict__ out) {
    float* ks = conv1_smem;          // [64i][64o] = 4096
    float* xs = conv1_smem + 4096;   // [64i][256px] = 16384
    int b = blockIdx.y;
    int p0 = blockIdx.x * 256;
    int tid = threadIdx.x;

    {
        const float4* ksrc = (const float4*)(g_k1 + b * 4096);
        float4* kdst = (float4*)ks;
#pragma unroll
        for (int i = 0; i < 4; i++) kdst[tid + 256 * i] = ksrc[tid + 256 * i];
        float4* xdst = (float4*)xs;
#pragma unroll
        for (int i = 0; i < 16; i++) {
            int idx = tid + 256 * i;           // f4 index in [0,4096)
            int row = idx >> 6, col = (idx & 63) << 2;
            xdst[idx] = *(const float4*)&x[((size_t)(b * 64 + row)) * HWSZ + p0 + col];
        }
    }
    __syncthreads();

    int og = (tid >> 5) << 3;    // warp -> 8 outputs
    int q0 = (tid & 31) << 2;    // lane -> px [q0..q0+3] and [q0+128..q0+131]
    float acc[8][8];
#pragma unroll
    for (int a = 0; a < 8; a++)
#pragma unroll
        for (int p = 0; p < 8; p++) acc[a][p] = 0.f;

#pragma unroll 8
    for (int i = 0; i < 64; i++) {
        float4 xa = *(const float4*)&xs[(i << 8) + q0];
        float4 xb = *(const float4*)&xs[(i << 8) + 128 + q0];
        float4 ka = *(const float4*)&ks[(i << 6) + og];
        float4 kb = *(const float4*)&ks[(i << 6) + og + 4];
        float kr[8] = {ka.x, ka.y, ka.z, ka.w, kb.x, kb.y, kb.z, kb.w};
        float xr[8] = {xa.x, xa.y, xa.z, xa.w, xb.x, xb.y, xb.z, xb.w};
#pragma unroll
        for (int a = 0; a < 8; a++)
#pragma unroll
            for (int p = 0; p < 8; p++) acc[a][p] = fmaf(kr[a], xr[p], acc[a][p]);
    }

#pragma unroll
    for (int a = 0; a < 8; a++) {
        int o = og + a;
        float sc = g1[o] * rsqrtf(v1[o] + EPSV);
        float sh = b1[o] - m1[o] * sc;
        float4 r0, r1q;
        r0.x = fmaxf(acc[a][0] + sh, 0.f);
        r0.y = fmaxf(acc[a][1] + sh, 0.f);
        r0.z = fmaxf(acc[a][2] + sh, 0.f);
        r0.w = fmaxf(acc[a][3] + sh, 0.f);
        r1q.x = fmaxf(acc[a][4] + sh, 0.f);
        r1q.y = fmaxf(acc[a][5] + sh, 0.f);
        r1q.z = fmaxf(acc[a][6] + sh, 0.f);
        r1q.w = fmaxf(acc[a][7] + sh, 0.f);
        float* op = out + ((size_t)(b * 128 + o)) * HWSZ + p0;
        *(float4*)&op[q0] = r0;
        *(float4*)&op[128 + q0] = r1q;
        float s = r0.x + r0.y + r0.z + r0.w + r1q.x + r1q.y + r1q.z + r1q.w;
        for (int o2 = 16; o2; o2 >>= 1) s += __shfl_xor_sync(0xffffffffu, s, o2);
        if ((tid & 31) == 0) atomicAdd(&g_sum1[b * 64 + o], s);
    }
}

// ---- dynamic 3x3 depthwise (k2 mix fused) + BN + ReLU + channel-sum ----
// grid (7 strips, NB*64), block 224; strip = 16 rows x 112 cols
#define DWST 120
__global__ __launch_bounds__(224) void dw_kernel(
    const float* __restrict__ rw2, const float* __restrict__ rb2,
    const float* __restrict__ w2,
    const float* __restrict__ g2, const float* __restrict__ b2,
    const float* __restrict__ m2, const float* __restrict__ v2,
    float* __restrict__ out) {
    __shared__ float sm[18 * DWST];
    __shared__ float r2s[4];
    __shared__ float kk[9];
    __shared__ float sh_bias;
    __shared__ float red[7];

    int bc = blockIdx.y;
    int b = bc >> 6, c = bc & 63;
    const float* in = out + ((size_t)(b * 128 + c)) * HWSZ;       // x1 channel
    float* op = out + ((size_t)(b * 128 + 64 + c)) * HWSZ;        // x2 channel
    int tid = threadIdx.x;
    int y0 = blockIdx.x * 16;

    if (tid < 4) {
        float a = rb2[tid];
        for (int cc = 0; cc < 64; cc++)
            a += g_sum1[b * 64 + cc] * (1.f / (float)HWSZ) * rw2[tid * 64 + cc];
        r2s[tid] = sigmoidf_(a);
    }
    // load 18 rows x 28 quads = 504 f4 with 224 threads
    for (int i = tid; i < 504; i += 224) {
        int r = i / 28, q = i % 28;
        int gy = y0 - 1 + r;
        float4 v;
        if (gy >= 0 && gy < IMGW) v = *(const float4*)&in[gy * IMGW + q * 4];
        else v = make_float4(0.f, 0.f, 0.f, 0.f);
        *(float4*)&sm[r * DWST + 4 + q * 4] = v;
    }
    for (int r = tid; r < 18; r += 224) { sm[r * DWST + 3] = 0.f; sm[r * DWST + 116] = 0.f; }
    __syncthreads();
    if (tid < 9) {
        float a = 0.f;
#pragma unroll
        for (int e = 0; e < 4; e++) a += r2s[e] * w2[e * 576 + c * 9 + tid];
        kk[tid] = a * (g2[c] * rsqrtf(v2[c] + EPSV));
    }
    if (tid == 9) {
        float sc = g2[c] * rsqrtf(v2[c] + EPSV);
        sh_bias = b2[c] - m2[c] * sc;
    }
    __syncthreads();

    int q = tid % 28;            // quad col
    int rr = tid / 28;           // 0..7
    int xb = 4 + q * 4;
    float tsum = 0.f;

#pragma unroll
    for (int half = 0; half < 2; half++) {
        int orow = rr + half * 8;               // output row in strip (0..15)
        float acc0 = sh_bias, acc1 = sh_bias, acc2 = sh_bias, acc3 = sh_bias;
#pragma unroll
        for (int dr = 0; dr < 3; dr++) {
            const float* row = &sm[(orow + dr) * DWST];
            float l = row[xb - 1];
            float4 m = *(const float4*)&row[xb];
            float rgt = row[xb + 4];
            float k0 = kk[dr * 3 + 0], k1 = kk[dr * 3 + 1], k2 = kk[dr * 3 + 2];
            acc0 = fmaf(k0, l,   fmaf(k1, m.x, fmaf(k2, m.y, acc0)));
            acc1 = fmaf(k0, m.x, fmaf(k1, m.y, fmaf(k2, m.z, acc1)));
            acc2 = fmaf(k0, m.y, fmaf(k1, m.z, fmaf(k2, m.w, acc2)));
            acc3 = fmaf(k0, m.z, fmaf(k1, m.w, fmaf(k2, rgt, acc3)));
        }
        float4 r;
        r.x = fmaxf(acc0, 0.f); r.y = fmaxf(acc1, 0.f);
        r.z = fmaxf(acc2, 0.f); r.w = fmaxf(acc3, 0.f);
        *(float4*)&op[(y0 + orow) * IMGW + q * 4] = r;
        tsum += r.x + r.y + r.z + r.w;
    }

    for (int o = 16; o; o >>= 1) tsum += __shfl_xor_sync(0xffffffffu, tsum, o);
    if ((tid & 31) == 0) red[tid >> 5] = tsum;
    __syncthreads();
    if (tid < 7) {
        float s = red[tid];
        for (int o = 4; o; o >>= 1) s += __shfl_xor_sync(0x7fu, s, o);
        if (tid == 0) atomicAdd(&g_sum2[bc], s);
    }
}

// ---- SE MLP -> gates: grid NB x 128, weights staged in smem ----
__global__ __launch_bounds__(128) void se_kernel(
    const float* __restrict__ sw1, const float* __restrict__ sb1,
    const float* __restrict__ sw2, const float* __restrict__ sb2) {
    int b = blockIdx.x;
    int tid = threadIdx.x;
    __shared__ float w1s[32 * 128];
    __shared__ float w2s[128 * 32];
    __shared__ float sm[128];
    __shared__ float h[32];
#pragma unroll
    for (int k = 0; k < 8; k++) {
        ((float4*)w1s)[tid + 128 * k] = ((const float4*)sw1)[tid + 128 * k];
        ((float4*)w2s)[tid + 128 * k] = ((const float4*)sw2)[tid + 128 * k];
    }
    sm[tid] = (tid < 64 ? g_sum1[b * 64 + tid] : g_sum2[b * 64 + tid - 64]) * (1.f / (float)HWSZ);
    __syncthreads();
    {
        int j = tid >> 2, l4 = tid & 3;
        float a = 0.f;
#pragma unroll
        for (int c = 0; c < 32; c++) a += w1s[j * 128 + l4 * 32 + c] * sm[l4 * 32 + c];
        a += __shfl_xor_sync(0xffffffffu, a, 1);
        a += __shfl_xor_sync(0xffffffffu, a, 2);
        if (l4 == 0) h[j] = fmaxf(a + sb1[j], 0.f);
    }
    __syncthreads();
    float a = sb2[tid];
#pragma unroll
    for (int j = 0; j < 32; j++) a += w2s[tid * 32 + j] * h[j];
    g_gates[b * 128 + tid] = sigmoidf_(a);
}

// ---- in-place gate scaling: grid (14, 2048) x 224, one f4/thread ----
__global__ __launch_bounds__(224) void scale_kernel(float* __restrict__ out) {
    int bc = blockIdx.y;
    int fq = blockIdx.x * 224 + threadIdx.x;     // 0..3135
    float g = __ldg(&g_gates[bc]);
    float4* p = ((float4*)out) + (size_t)bc * (HWSZ / 4) + fq;
    float4 v = *p;
    v.x *= g; v.y *= g; v.z *= g; v.w *= g;
    *p = v;
}

// ---------------------------------------------------------------
extern "C" void kernel_launch(void* const* d_in, const int* in_sizes, int n_in,
                              void* d_out, int out_size) {
    const float* x    = (const float*)d_in[0];
    const float* rw1  = (const float*)d_in[1];
    const float* rb1  = (const float*)d_in[2];
    const float* w1   = (const float*)d_in[3];
    const float* bn1g = (const float*)d_in[4];
    const float* bn1b = (const float*)d_in[5];
    const float* bn1m = (const float*)d_in[6];
    const float* bn1v = (const float*)d_in[7];
    const float* rw2  = (const float*)d_in[8];
    const float* rb2  = (const float*)d_in[9];
    const float* w2   = (const float*)d_in[10];
    const float* bn2g = (const float*)d_in[11];
    const float* bn2b = (const float*)d_in[12];
    const float* bn2m = (const float*)d_in[13];
    const float* bn2v = (const float*)d_in[14];
    const float* sw1  = (const float*)d_in[15];
    const float* sb1  = (const float*)d_in[16];
    const float* sw2  = (const float*)d_in[17];
    const float* sb2  = (const float*)d_in[18];
    float* out = (float*)d_out;

    const int conv1_smem_bytes = (4096 + 16384) * sizeof(float);
    cudaFuncSetAttribute(conv1_kernel, cudaFuncAttributeMaxDynamicSharedMemorySize,
                         conv1_smem_bytes);

    pool1_kernel<<<NB * 64, 256>>>(x);
    build_k1_kernel<<<NB, 256>>>(rw1, rb1, w1, bn1g, bn1v);
    conv1_kernel<<<dim3(HWSZ / 256, NB), 256, conv1_smem_bytes>>>(
        x, bn1g, bn1b, bn1m, bn1v, out);
    dw_kernel<<<dim3(7, NB * 64), 224>>>(
        rw2, rb2, w2, bn2g, bn2b, bn2m, bn2v, out);
    se_kernel<<<NB, 128>>>(sw1, sb1, sw2, sb2);
    scale_kernel<<<dim3(14, NB * 128), 224>>>(out);
}

// round 6
// speedup vs baseline: 2.1263x; 1.1100x over previous
#include <cuda_runtime.h>
#include <math.h>

#define HWSZ 12544      // 112*112
#define IMGW 112
#define NB   16
#define EPSV 1e-5f

// ---- scratch (tiny) ----
__device__ float g_pooled[NB * 64];
__device__ float g_k1[NB * 64 * 64];   // [b][i][o], BN1 scale folded
__device__ float g_sum1[NB * 64];      // post-act x1 channel sums
__device__ float g_sum2[NB * 64];      // post-act x2 channel sums
__device__ float g_gates[NB * 128];

__device__ __forceinline__ float sigmoidf_(float x) { return 1.f / (1.f + expf(-x)); }

// ---- mean over HW per (b,c) + zero sums: grid 1024 x 256 ----
__global__ __launch_bounds__(256) void pool1_kernel(const float* __restrict__ x) {
    int bc = blockIdx.x;
    if (threadIdx.x == 0) { g_sum1[bc] = 0.f; g_sum2[bc] = 0.f; }
    const float4* p = (const float4*)(x + (size_t)bc * HWSZ);
    float s = 0.f;
    for (int i = threadIdx.x; i < HWSZ / 4; i += 256) {
        float4 v = p[i];
        s += v.x + v.y + v.z + v.w;
    }
    for (int o = 16; o; o >>= 1) s += __shfl_xor_sync(0xffffffffu, s, o);
    __shared__ float red[8];
    if ((threadIdx.x & 31) == 0) red[threadIdx.x >> 5] = s;
    __syncthreads();
    if (threadIdx.x < 8) {
        s = red[threadIdx.x];
        for (int o = 4; o; o >>= 1) s += __shfl_xor_sync(0xffu, s, o);
        if (threadIdx.x == 0) g_pooled[bc] = s * (1.f / (float)HWSZ);
    }
}

// ---- r1 + mixed 1x1 kernel (BN1 scale folded): grid NB x 256 ----
__global__ __launch_bounds__(256) void build_k1_kernel(
    const float* __restrict__ rw1, const float* __restrict__ rb1,
    const float* __restrict__ w1,
    const float* __restrict__ g1, const float* __restrict__ v1) {
    int b = blockIdx.x;
    __shared__ float r1s[4];
    if (threadIdx.x < 4) {
        int e = threadIdx.x;
        float a = rb1[e];
        for (int i = 0; i < 64; i++) a += g_pooled[b * 64 + i] * rw1[e * 64 + i];
        r1s[e] = sigmoidf_(a);
    }
    __syncthreads();
    for (int idx = threadIdx.x; idx < 4096; idx += 256) {
        int i = idx >> 6, o = idx & 63;
        float a = 0.f;
#pragma unroll
        for (int e = 0; e < 4; e++) a += r1s[e] * w1[e * 4096 + o * 64 + i];
        float sc = g1[o] * rsqrtf(v1[o] + EPSV);
        g_k1[b * 4096 + idx] = a * sc;    // layout [i][o]
    }
}

// ---- dynamic 1x1 conv + BN + ReLU + channel-sum (proven version) ----
// tile: 64 outputs x 256 pixels; per lane 8 out x 8 px. grid (49, NB) x 256
extern __shared__ float conv1_smem[];
__global__ __launch_bounds__(256, 2) void conv1_kernel(
    const float* __restrict__ x,
    const float* __restrict__ g1, const float* __restrict__ b1,
    const float* __restrict__ m1, const float* __restrict__ v1,
    float* __restrict__ out) {
    float* ks = conv1_smem;          // [64i][64o] = 4096
    float* xs = conv1_smem + 4096;   // [64i][256px] = 16384
    int b = blockIdx.y;
    int p0 = blockIdx.x * 256;
    int tid = threadIdx.x;

    {
        const float4* ksrc = (const float4*)(g_k1 + b * 4096);
        float4* kdst = (float4*)ks;
#pragma unroll
        for (int i = 0; i < 4; i++) kdst[tid + 256 * i] = ksrc[tid + 256 * i];
        float4* xdst = (float4*)xs;
#pragma unroll
        for (int i = 0; i < 16; i++) {
            int idx = tid + 256 * i;           // f4 index in [0,4096)
            int row = idx >> 6, col = (idx & 63) << 2;
            xdst[idx] = *(const float4*)&x[((size_t)(b * 64 + row)) * HWSZ + p0 + col];
        }
    }
    __syncthreads();

    int og = (tid >> 5) << 3;    // warp -> 8 outputs
    int q0 = (tid & 31) << 2;    // lane -> px [q0..q0+3] and [q0+128..q0+131]
    float acc[8][8];
#pragma unroll
    for (int a = 0; a < 8; a++)
#pragma unroll
        for (int p = 0; p < 8; p++) acc[a][p] = 0.f;

#pragma unroll 8
    for (int i = 0; i < 64; i++) {
        float4 xa = *(const float4*)&xs[(i << 8) + q0];
        float4 xb = *(const float4*)&xs[(i << 8) + 128 + q0];
        float4 ka = *(const float4*)&ks[(i << 6) + og];
        float4 kb = *(const float4*)&ks[(i << 6) + og + 4];
        float kr[8] = {ka.x, ka.y, ka.z, ka.w, kb.x, kb.y, kb.z, kb.w};
        float xr[8] = {xa.x, xa.y, xa.z, xa.w, xb.x, xb.y, xb.z, xb.w};
#pragma unroll
        for (int a = 0; a < 8; a++)
#pragma unroll
            for (int p = 0; p < 8; p++) acc[a][p] = fmaf(kr[a], xr[p], acc[a][p]);
    }

#pragma unroll
    for (int a = 0; a < 8; a++) {
        int o = og + a;
        float sc = g1[o] * rsqrtf(v1[o] + EPSV);
        float sh = b1[o] - m1[o] * sc;
        float4 r0, r1q;
        r0.x = fmaxf(acc[a][0] + sh, 0.f);
        r0.y = fmaxf(acc[a][1] + sh, 0.f);
        r0.z = fmaxf(acc[a][2] + sh, 0.f);
        r0.w = fmaxf(acc[a][3] + sh, 0.f);
        r1q.x = fmaxf(acc[a][4] + sh, 0.f);
        r1q.y = fmaxf(acc[a][5] + sh, 0.f);
        r1q.z = fmaxf(acc[a][6] + sh, 0.f);
        r1q.w = fmaxf(acc[a][7] + sh, 0.f);
        float* op = out + ((size_t)(b * 128 + o)) * HWSZ + p0;
        *(float4*)&op[q0] = r0;
        *(float4*)&op[128 + q0] = r1q;
        float s = r0.x + r0.y + r0.z + r0.w + r1q.x + r1q.y + r1q.z + r1q.w;
        for (int o2 = 16; o2; o2 >>= 1) s += __shfl_xor_sync(0xffffffffu, s, o2);
        if ((tid & 31) == 0) atomicAdd(&g_sum1[b * 64 + o], s);
    }
}

// ---- dynamic 3x3 depthwise: register-rolling stencil, no smem ----
// one warp = one (channel, 16-row strip); 28 active lanes x 4 cols = 112 cols
// grid 896 x 256 (8 warps/block, 7168 warps = 1024 channels x 7 strips)
__global__ __launch_bounds__(256) void dw_kernel(
    const float* __restrict__ rw2, const float* __restrict__ rb2,
    const float* __restrict__ w2,
    const float* __restrict__ g2, const float* __restrict__ b2,
    const float* __restrict__ m2, const float* __restrict__ v2,
    float* __restrict__ out) {
    const unsigned FULL = 0xffffffffu;
    int lane = threadIdx.x & 31;
    int gw = blockIdx.x * 8 + (threadIdx.x >> 5);   // 0..7167
    int bc = gw / 7, s7 = gw % 7;
    int b = bc >> 6, c = bc & 63;
    const float* in = out + ((size_t)(b * 128 + c)) * HWSZ;       // x1 channel
    float* op = out + ((size_t)(b * 128 + 64 + c)) * HWSZ;        // x2 channel

    // per-warp k2 mix: lanes 0-3 compute expert routing, lanes 0-8 the coeffs
    float r2 = 0.f;
    if (lane < 4) {
        float a = rb2[lane];
        const float* rw = rw2 + lane * 64;
        const float* su = g_sum1 + b * 64;
#pragma unroll 8
        for (int cc = 0; cc < 64; cc++) a += su[cc] * (1.f / (float)HWSZ) * rw[cc];
        r2 = sigmoidf_(a);
    }
    float sc = g2[c] * rsqrtf(v2[c] + EPSV);
    float kv = 0.f;
    {
        float e0 = __shfl_sync(FULL, r2, 0), e1 = __shfl_sync(FULL, r2, 1);
        float e2 = __shfl_sync(FULL, r2, 2), e3 = __shfl_sync(FULL, r2, 3);
        if (lane < 9) {
            const float* wp = w2 + c * 9 + lane;
            kv = (e0 * wp[0] + e1 * wp[576] + e2 * wp[1152] + e3 * wp[1728]) * sc;
        }
    }
    float k0 = __shfl_sync(FULL, kv, 0), k1 = __shfl_sync(FULL, kv, 1), k2 = __shfl_sync(FULL, kv, 2);
    float k3 = __shfl_sync(FULL, kv, 3), k4 = __shfl_sync(FULL, kv, 4), k5 = __shfl_sync(FULL, kv, 5);
    float k6 = __shfl_sync(FULL, kv, 6), k7 = __shfl_sync(FULL, kv, 7), k8 = __shfl_sync(FULL, kv, 8);
    float bias = b2[c] - m2[c] * sc;

    bool act = lane < 28;
    int col = lane * 4;
    int y0 = s7 * 16;

    float4 Am, Bm, Cm;
    float Al, Ar, Bl, Br, Cl, Cr;

#define LDROW(y, M, L, R) do {                                              \
        float4 _v = make_float4(0.f, 0.f, 0.f, 0.f);                        \
        int _y = (y);                                                       \
        if (act && _y >= 0 && _y < IMGW)                                    \
            _v = *(const float4*)&in[_y * IMGW + col];                      \
        M = _v;                                                             \
        float _u = __shfl_up_sync(FULL, _v.w, 1);                           \
        L = (lane == 0) ? 0.f : _u;                                         \
        R = __shfl_down_sync(FULL, _v.x, 1);                                \
    } while (0)

    LDROW(y0 - 1, Am, Al, Ar);
    LDROW(y0,     Bm, Bl, Br);

    float tsum = 0.f;
#pragma unroll 4
    for (int i = 0; i < 16; i++) {
        LDROW(y0 + i + 1, Cm, Cl, Cr);
        float a0 = bias, a1 = bias, a2 = bias, a3 = bias;
        a0 = fmaf(k0, Al,   fmaf(k1, Am.x, fmaf(k2, Am.y, a0)));
        a1 = fmaf(k0, Am.x, fmaf(k1, Am.y, fmaf(k2, Am.z, a1)));
        a2 = fmaf(k0, Am.y, fmaf(k1, Am.z, fmaf(k2, Am.w, a2)));
        a3 = fmaf(k0, Am.z, fmaf(k1, Am.w, fmaf(k2, Ar,   a3)));
        a0 = fmaf(k3, Bl,   fmaf(k4, Bm.x, fmaf(k5, Bm.y, a0)));
        a1 = fmaf(k3, Bm.x, fmaf(k4, Bm.y, fmaf(k5, Bm.z, a1)));
        a2 = fmaf(k3, Bm.y, fmaf(k4, Bm.z, fmaf(k5, Bm.w, a2)));
        a3 = fmaf(k3, Bm.z, fmaf(k4, Bm.w, fmaf(k5, Br,   a3)));
        a0 = fmaf(k6, Cl,   fmaf(k7, Cm.x, fmaf(k8, Cm.y, a0)));
        a1 = fmaf(k6, Cm.x, fmaf(k7, Cm.y, fmaf(k8, Cm.z, a1)));
        a2 = fmaf(k6, Cm.y, fmaf(k7, Cm.z, fmaf(k8, Cm.w, a2)));
        a3 = fmaf(k6, Cm.z, fmaf(k7, Cm.w, fmaf(k8, Cr,   a3)));
        float4 r;
        r.x = fmaxf(a0, 0.f); r.y = fmaxf(a1, 0.f);
        r.z = fmaxf(a2, 0.f); r.w = fmaxf(a3, 0.f);
        if (act) {
            *(float4*)&op[(y0 + i) * IMGW + col] = r;
            tsum += r.x + r.y + r.z + r.w;
        }
        Am = Bm; Al = Bl; Ar = Br;
        Bm = Cm; Bl = Cl; Br = Cr;
    }
#undef LDROW

    for (int o = 16; o; o >>= 1) tsum += __shfl_xor_sync(FULL, tsum, o);
    if (lane == 0) atomicAdd(&g_sum2[bc], tsum);
}

// ---- SE MLP -> gates: grid NB x 128, weights staged in smem ----
__global__ __launch_bounds__(128) void se_kernel(
    const float* __restrict__ sw1, const float* __restrict__ sb1,
    const float* __restrict__ sw2, const float* __restrict__ sb2) {
    int b = blockIdx.x;
    int tid = threadIdx.x;
    __shared__ float w1s[32 * 128];
    __shared__ float w2s[128 * 32];
    __shared__ float sm[128];
    __shared__ float h[32];
#pragma unroll
    for (int k = 0; k < 8; k++) {
        ((float4*)w1s)[tid + 128 * k] = ((const float4*)sw1)[tid + 128 * k];
        ((float4*)w2s)[tid + 128 * k] = ((const float4*)sw2)[tid + 128 * k];
    }
    sm[tid] = (tid < 64 ? g_sum1[b * 64 + tid] : g_sum2[b * 64 + tid - 64]) * (1.f / (float)HWSZ);
    __syncthreads();
    {
        int j = tid >> 2, l4 = tid & 3;
        float a = 0.f;
#pragma unroll
        for (int c = 0; c < 32; c++) a += w1s[j * 128 + l4 * 32 + c] * sm[l4 * 32 + c];
        a += __shfl_xor_sync(0xffffffffu, a, 1);
        a += __shfl_xor_sync(0xffffffffu, a, 2);
        if (l4 == 0) h[j] = fmaxf(a + sb1[j], 0.f);
    }
    __syncthreads();
    float a = sb2[tid];
#pragma unroll
    for (int j = 0; j < 32; j++) a += w2s[tid * 32 + j] * h[j];
    g_gates[b * 128 + tid] = sigmoidf_(a);
}

// ---- in-place gate scaling: grid (14, 2048) x 224, one f4/thread ----
__global__ __launch_bounds__(224) void scale_kernel(float* __restrict__ out) {
    int bc = blockIdx.y;
    int fq = blockIdx.x * 224 + threadIdx.x;     // 0..3135
    float g = __ldg(&g_gates[bc]);
    float4* p = ((float4*)out) + (size_t)bc * (HWSZ / 4) + fq;
    float4 v = *p;
    v.x *= g; v.y *= g; v.z *= g; v.w *= g;
    *p = v;
}

// ---------------------------------------------------------------
extern "C" void kernel_launch(void* const* d_in, const int* in_sizes, int n_in,
                              void* d_out, int out_size) {
    const float* x    = (const float*)d_in[0];
    const float* rw1  = (const float*)d_in[1];
    const float* rb1  = (const float*)d_in[2];
    const float* w1   = (const float*)d_in[3];
    const float* bn1g = (const float*)d_in[4];
    const float* bn1b = (const float*)d_in[5];
    const float* bn1m = (const float*)d_in[6];
    const float* bn1v = (const float*)d_in[7];
    const float* rw2  = (const float*)d_in[8];
    const float* rb2  = (const float*)d_in[9];
    const float* w2   = (const float*)d_in[10];
    const float* bn2g = (const float*)d_in[11];
    const float* bn2b = (const float*)d_in[12];
    const float* bn2m = (const float*)d_in[13];
    const float* bn2v = (const float*)d_in[14];
    const float* sw1  = (const float*)d_in[15];
    const float* sb1  = (const float*)d_in[16];
    const float* sw2  = (const float*)d_in[17];
    const float* sb2  = (const float*)d_in[18];
    float* out = (float*)d_out;

    const int conv1_smem_bytes = (4096 + 16384) * sizeof(float);
    cudaFuncSetAttribute(conv1_kernel, cudaFuncAttributeMaxDynamicSharedMemorySize,
                         conv1_smem_bytes);

    pool1_kernel<<<NB * 64, 256>>>(x);
    build_k1_kernel<<<NB, 256>>>(rw1, rb1, w1, bn1g, bn1v);
    conv1_kernel<<<dim3(HWSZ / 256, NB), 256, conv1_smem_bytes>>>(
        x, bn1g, bn1b, bn1m, bn1v, out);
    dw_kernel<<<896, 256>>>(
        rw2, rb2, w2, bn2g, bn2b, bn2m, bn2v, out);
    se_kernel<<<NB, 128>>>(sw1, sb1, sw2, sb2);
    scale_kernel<<<dim3(14, NB * 128), 224>>>(out);
}